// round 8
// baseline (speedup 1.0000x reference)
#include <cuda_runtime.h>
#include <stdint.h>
#include <math.h>

#define SCALING 2.0f
#define MAXM 32768
#define MAXD 1024

// Static scratch (allocation-free per harness rules)
__device__ int8_t g_Xh[(size_t)MAXM * MAXD];
__device__ int8_t g_Xl[(size_t)MAXM * MAXD];
__device__ int8_t g_Wh[(size_t)MAXD * MAXD];
__device__ int8_t g_Wl[(size_t)MAXD * MAXD];
__device__ float  g_sx[MAXM];
__device__ float  g_sw[MAXD];

// q in [-16256,16256] -> h*128 + l, h in [-127,127], l in [-64,64]
__device__ __forceinline__ void quant2(float q, int& h, int& l) {
    float hf = rintf(q * (1.f / 128.f));
    h = (int)hf;
    l = (int)rintf(q - 128.f * hf);
}

// ============================ Prep (weight) ============================
// w_eff = W[o,:] + 2*b[o,:]@A; scale by mag/||w_eff||; int8 2-word quantize.
__global__ void prep_kernel(const float* __restrict__ weight,
                            const float* __restrict__ a_w,
                            const float* __restrict__ b_w,
                            const float* __restrict__ magnitude,
                            int D_IN, int R) {
    int o = blockIdx.x;
    int tid = threadIdx.x;
    __shared__ float bs[32];
    __shared__ float red[34];
    if (tid < R) bs[tid] = b_w[o * R + tid];
    __syncthreads();

    float wv[4];
    float sumsq = 0.f;
    int cnt = 0;
    for (int d = tid; d < D_IN; d += 256, ++cnt) {
        float corr = 0.f;
        #pragma unroll 16
        for (int r = 0; r < R; ++r) corr += bs[r] * a_w[(size_t)r * D_IN + d];
        float w = weight[(size_t)o * D_IN + d] + SCALING * corr;
        wv[cnt] = w;
        sumsq += w * w;
    }
    #pragma unroll
    for (int off = 16; off; off >>= 1)
        sumsq += __shfl_down_sync(0xffffffffu, sumsq, off);
    if ((tid & 31) == 0) red[tid >> 5] = sumsq;
    __syncthreads();
    if (tid < 32) {
        float v = (tid < 8) ? red[tid] : 0.f;
        #pragma unroll
        for (int off = 16; off; off >>= 1)
            v += __shfl_down_sync(0xffffffffu, v, off);
        if (tid == 0) red[32] = v;
    }
    __syncthreads();
    float scale = magnitude[o] * rsqrtf(red[32]);

    // row max of |w*scale|
    float rmax = 0.f;
    #pragma unroll
    for (int i = 0; i < 4; ++i) rmax = fmaxf(rmax, fabsf(wv[i] * scale));
    #pragma unroll
    for (int off = 16; off; off >>= 1)
        rmax = fmaxf(rmax, __shfl_down_sync(0xffffffffu, rmax, off));
    if ((tid & 31) == 0) red[tid >> 5] = rmax;
    __syncthreads();
    if (tid < 32) {
        float v = (tid < 8) ? red[tid] : 0.f;
        #pragma unroll
        for (int off = 16; off; off >>= 1)
            v = fmaxf(v, __shfl_down_sync(0xffffffffu, v, off));
        if (tid == 0) red[33] = v;
    }
    __syncthreads();
    float m = red[33];
    float inv = (m > 0.f) ? (16256.f / m) : 0.f;
    if (tid == 0) g_sw[o] = m * (1.f / 16256.f);

    cnt = 0;
    for (int d = tid; d < D_IN; d += 256, ++cnt) {
        int h, l;
        quant2(wv[cnt] * scale * inv, h, l);
        g_Wh[(size_t)o * D_IN + d] = (int8_t)h;
        g_Wl[(size_t)o * D_IN + d] = (int8_t)l;
    }
}

// ============================ X quantization ============================
// One block per x-row: rowmax, then 2-word int8 quantize. 4 elems/thread.
__global__ void quant_x_kernel(const float* __restrict__ x, int K) {
    int m = blockIdx.x;
    int tid = threadIdx.x;
    __shared__ float red[9];

    const float4 v = *(const float4*)(x + (size_t)m * K + tid * 4);
    float rmax = fmaxf(fmaxf(fabsf(v.x), fabsf(v.y)),
                       fmaxf(fabsf(v.z), fabsf(v.w)));
    #pragma unroll
    for (int off = 16; off; off >>= 1)
        rmax = fmaxf(rmax, __shfl_down_sync(0xffffffffu, rmax, off));
    if ((tid & 31) == 0) red[tid >> 5] = rmax;
    __syncthreads();
    if (tid < 32) {
        float t = (tid < 8) ? red[tid] : 0.f;
        #pragma unroll
        for (int off = 16; off; off >>= 1)
            t = fmaxf(t, __shfl_down_sync(0xffffffffu, t, off));
        if (tid == 0) red[8] = t;
    }
    __syncthreads();
    float mx = red[8];
    float inv = (mx > 0.f) ? (16256.f / mx) : 0.f;
    if (tid == 0) g_sx[m] = mx * (1.f / 16256.f);

    int h0, l0, h1, l1, h2, l2, h3, l3;
    quant2(v.x * inv, h0, l0);
    quant2(v.y * inv, h1, l1);
    quant2(v.z * inv, h2, l2);
    quant2(v.w * inv, h3, l3);
    uint32_t hp = (uint32_t)(h0 & 255) | ((uint32_t)(h1 & 255) << 8) |
                  ((uint32_t)(h2 & 255) << 16) | ((uint32_t)h3 << 24);
    uint32_t lp = (uint32_t)(l0 & 255) | ((uint32_t)(l1 & 255) << 8) |
                  ((uint32_t)(l2 & 255) << 16) | ((uint32_t)l3 << 24);
    *(uint32_t*)(g_Xh + (size_t)m * K + tid * 4) = hp;
    *(uint32_t*)(g_Xl + (size_t)m * K + tid * 4) = lp;
}

// ============================ IMMA GEMM ============================
// acc_hh += Xh@Wh^T ; acc_mx += Xh@Wl^T + Xl@Wh^T  (s32 exact)
// out = sx[m]*sw[n]*(16384*hh + 128*mx)
// CTA 128x128, 8 warps (2m x 4n), warp tile 64x32; K-chunk 32 (one IMMA k);
// 4-stage cp.async, 16KB/stage. Rows are 32B; 1-bit XOR swizzle on the two
// 16B halves keeps ldmatrix conflict-free.
#define BM 128
#define BN 128
#define BK 32
#define STAGES 4
#define T_BYTES (128 * 32)                 // 4 KB per tile
#define STAGE_BYTES (4 * T_BYTES)          // 16 KB: Ah, Al, Bh, Bl
#define SMEM_TOTAL (STAGES * STAGE_BYTES)  // 64 KB
#define AH_OFF 0
#define AL_OFF T_BYTES
#define BH_OFF (2 * T_BYTES)
#define BL_OFF (3 * T_BYTES)

__device__ __forceinline__ uint32_t smem_u32(const void* p) {
    uint32_t a;
    asm("{ .reg .u64 t; cvta.to.shared.u64 t, %1; cvt.u32.u64 %0, t; }"
        : "=r"(a) : "l"(p));
    return a;
}
__device__ __forceinline__ void cp16(uint32_t dst, const void* src) {
    asm volatile("cp.async.cg.shared.global [%0], [%1], 16;"
                 :: "r"(dst), "l"(src) : "memory");
}
__device__ __forceinline__ void cp_commit() {
    asm volatile("cp.async.commit_group;" ::: "memory");
}
template <int N_>
__device__ __forceinline__ void cp_wait() {
    asm volatile("cp.async.wait_group %0;" :: "n"(N_) : "memory");
}
__device__ __forceinline__ void ldsm_x4(uint32_t& r0, uint32_t& r1,
                                        uint32_t& r2, uint32_t& r3, uint32_t a) {
    asm volatile("ldmatrix.sync.aligned.m8n8.x4.shared.b16 {%0,%1,%2,%3}, [%4];"
                 : "=r"(r0), "=r"(r1), "=r"(r2), "=r"(r3) : "r"(a));
}
__device__ __forceinline__ void imma(int* c, const uint32_t a0, const uint32_t a1,
                                     const uint32_t a2, const uint32_t a3,
                                     uint32_t b0, uint32_t b1) {
    asm volatile(
        "mma.sync.aligned.m16n8k32.row.col.s32.s8.s8.s32 "
        "{%0,%1,%2,%3}, {%4,%5,%6,%7}, {%8,%9}, {%0,%1,%2,%3};"
        : "+r"(c[0]), "+r"(c[1]), "+r"(c[2]), "+r"(c[3])
        : "r"(a0), "r"(a1), "r"(a2), "r"(a3), "r"(b0), "r"(b1));
}
// swizzled offset of 16B chunk c within 32B-row tile
__device__ __forceinline__ uint32_t sw_off8(int row, int c) {
    return (uint32_t)(row * 32 + ((c ^ ((row >> 2) & 1)) << 4));
}

__global__ void __launch_bounds__(256, 1)
gemm_imma_kernel(const float* __restrict__ sx_dummy,  // keep signature simple
                 float* __restrict__ out, int M, int N, int K) {
    extern __shared__ char smem[];
    const uint32_t sb = smem_u32(smem);
    const int tid = threadIdx.x;
    const int wid = tid >> 5;
    const int lane = tid & 31;
    const int wm = (wid & 1) * 64;
    const int wn = (wid >> 1) * 32;
    const int m0 = blockIdx.y * BM;
    const int n0 = blockIdx.x * BN;

    const int nchunk = K / BK;   // 32

    auto issue = [&](int c, int stage) {
        int kofs = c * BK;
        uint32_t base = sb + stage * STAGE_BYTES;
        #pragma unroll
        for (int j = 0; j < 4; ++j) {
            int u = tid + 256 * j;            // 0..1023
            int tile = u >> 8;                // 0:Ah 1:Al 2:Bh 3:Bl
            int v = u & 255;
            int row = v >> 1, ch = v & 1;
            uint32_t so = sw_off8(row, ch) + (uint32_t)tile * T_BYTES;
            const int8_t* src;
            if (tile == 0)      src = g_Xh + (size_t)(m0 + row) * K + kofs + ch * 16;
            else if (tile == 1) src = g_Xl + (size_t)(m0 + row) * K + kofs + ch * 16;
            else if (tile == 2) src = g_Wh + (size_t)(n0 + row) * K + kofs + ch * 16;
            else                src = g_Wl + (size_t)(n0 + row) * K + kofs + ch * 16;
            cp16(base + so, src);
        }
        cp_commit();
    };

    int ahh[16][4], amx[16][4];
    #pragma unroll
    for (int i = 0; i < 16; ++i)
        #pragma unroll
        for (int q = 0; q < 4; ++q) { ahh[i][q] = 0; amx[i][q] = 0; }

    issue(0, 0); issue(1, 1); issue(2, 2);

    // ldsm lane addressing (constant per thread)
    const int lsub = lane >> 3;          // matrix index 0..3
    const int lrow8 = lane & 7;
    const int arow_r = (lsub & 1) * 8 + lrow8;   // row within 16-row block
    const int ahalf = lsub >> 1;                  // k-half

    for (int c = 0; c < nchunk; ++c) {
        cp_wait<STAGES - 2>();
        __syncthreads();
        if (c + 3 < nchunk) issue(c + 3, (c + 3) % STAGES);

        uint32_t base = sb + (c % STAGES) * STAGE_BYTES;

        uint32_t ah[4][4], al[4][4], bh[2][4], bl[2][4];
        #pragma unroll
        for (int mf = 0; mf < 4; ++mf) {
            int row = wm + mf * 16 + arow_r;
            uint32_t so = sw_off8(row, ahalf);
            ldsm_x4(ah[mf][0], ah[mf][1], ah[mf][2], ah[mf][3],
                    base + AH_OFF + so);
            ldsm_x4(al[mf][0], al[mf][1], al[mf][2], al[mf][3],
                    base + AL_OFF + so);
        }
        #pragma unroll
        for (int p = 0; p < 2; ++p) {
            int row = wn + p * 16 + arow_r;
            uint32_t so = sw_off8(row, ahalf);
            ldsm_x4(bh[p][0], bh[p][1], bh[p][2], bh[p][3],
                    base + BH_OFF + so);
            ldsm_x4(bl[p][0], bl[p][1], bl[p][2], bl[p][3],
                    base + BL_OFF + so);
        }

        // hh -> acc_hh (16 mma, no same-acc adjacency)
        #pragma unroll
        for (int mf = 0; mf < 4; ++mf)
            #pragma unroll
            for (int p = 0; p < 2; ++p) {
                imma(ahh[mf * 4 + 2 * p],     ah[mf][0], ah[mf][1], ah[mf][2], ah[mf][3],
                     bh[p][0], bh[p][2]);
                imma(ahh[mf * 4 + 2 * p + 1], ah[mf][0], ah[mf][1], ah[mf][2], ah[mf][3],
                     bh[p][1], bh[p][3]);
            }
        // hl -> acc_mx
        #pragma unroll
        for (int mf = 0; mf < 4; ++mf)
            #pragma unroll
            for (int p = 0; p < 2; ++p) {
                imma(amx[mf * 4 + 2 * p],     ah[mf][0], ah[mf][1], ah[mf][2], ah[mf][3],
                     bl[p][0], bl[p][2]);
                imma(amx[mf * 4 + 2 * p + 1], ah[mf][0], ah[mf][1], ah[mf][2], ah[mf][3],
                     bl[p][1], bl[p][3]);
            }
        // lh -> acc_mx
        #pragma unroll
        for (int mf = 0; mf < 4; ++mf)
            #pragma unroll
            for (int p = 0; p < 2; ++p) {
                imma(amx[mf * 4 + 2 * p],     al[mf][0], al[mf][1], al[mf][2], al[mf][3],
                     bh[p][0], bh[p][2]);
                imma(amx[mf * 4 + 2 * p + 1], al[mf][0], al[mf][1], al[mf][2], al[mf][3],
                     bh[p][1], bh[p][3]);
            }
    }
    cp_wait<0>();

    // Epilogue: out = sx[m]*sw[n]*(16384*hh + 128*mx)
    #pragma unroll
    for (int mf = 0; mf < 4; ++mf) {
        int r0 = m0 + wm + mf * 16 + (lane >> 2);
        float sx0 = g_sx[r0];
        float sx1 = g_sx[r0 + 8];
        #pragma unroll
        for (int p8 = 0; p8 < 4; ++p8) {
            int idx = mf * 4 + p8;
            int c0 = n0 + wn + p8 * 8 + (lane & 3) * 2;
            float2 sw2 = *(const float2*)(g_sw + c0);
            float2 v0, v1;
            v0.x = sx0 * sw2.x * (16384.f * (float)ahh[idx][0] + 128.f * (float)amx[idx][0]);
            v0.y = sx0 * sw2.y * (16384.f * (float)ahh[idx][1] + 128.f * (float)amx[idx][1]);
            v1.x = sx1 * sw2.x * (16384.f * (float)ahh[idx][2] + 128.f * (float)amx[idx][2]);
            v1.y = sx1 * sw2.y * (16384.f * (float)ahh[idx][3] + 128.f * (float)amx[idx][3]);
            *(float2*)(out + (size_t)r0 * N + c0) = v0;
            *(float2*)(out + (size_t)(r0 + 8) * N + c0) = v1;
        }
    }
}

// ============================ launch ============================
extern "C" void kernel_launch(void* const* d_in, const int* in_sizes, int n_in,
                              void* d_out, int out_size) {
    const float* x      = (const float*)d_in[0];
    const float* weight = (const float*)d_in[1];
    const float* a_w    = (const float*)d_in[2];
    const float* b_w    = (const float*)d_in[3];
    const float* mag    = (const float*)d_in[4];
    float* out          = (float*)d_out;

    int D_OUT = in_sizes[4];
    int R     = in_sizes[3] / D_OUT;
    int D_IN  = in_sizes[2] / R;
    int M     = in_sizes[0] / D_IN;

    cudaFuncSetAttribute(gemm_imma_kernel,
                         cudaFuncAttributeMaxDynamicSharedMemorySize, SMEM_TOTAL);

    prep_kernel<<<D_OUT, 256>>>(weight, a_w, b_w, mag, D_IN, R);
    quant_x_kernel<<<M, 256>>>(x, D_IN);

    dim3 grid(D_OUT / BN, M / BM);
    gemm_imma_kernel<<<grid, 256, SMEM_TOTAL>>>(nullptr, out, M, D_OUT, D_IN);
}

// round 10
// speedup vs baseline: 5.8127x; 5.8127x over previous
#include <cuda_runtime.h>
#include <cuda_fp16.h>
#include <stdint.h>
#include <math.h>

#define SCALING 2.0f
#define MAXM 32768
#define MAXD 1024

// Static scratch (allocation-free per harness rules)
__device__ __half g_Xh[(size_t)MAXM * MAXD];
__device__ __half g_Wh[(size_t)MAXD * MAXD];

// ============================ Prep ============================
// w_eff = W[o,:] + 2*b[o,:]@A; scale by mag/||w_eff||; round to fp16.
__global__ void prep_kernel(const float* __restrict__ weight,
                            const float* __restrict__ a_w,
                            const float* __restrict__ b_w,
                            const float* __restrict__ magnitude,
                            int D_IN, int R) {
    int o = blockIdx.x;
    int tid = threadIdx.x;
    __shared__ float bs[32];
    __shared__ float red[33];
    if (tid < R) bs[tid] = b_w[o * R + tid];
    __syncthreads();

    float wv[4];
    float sumsq = 0.f;
    int cnt = 0;
    for (int d = tid; d < D_IN; d += 256, ++cnt) {
        float corr = 0.f;
        #pragma unroll 16
        for (int r = 0; r < R; ++r) corr += bs[r] * a_w[(size_t)r * D_IN + d];
        float w = weight[(size_t)o * D_IN + d] + SCALING * corr;
        wv[cnt] = w;
        sumsq += w * w;
    }
    #pragma unroll
    for (int off = 16; off; off >>= 1)
        sumsq += __shfl_down_sync(0xffffffffu, sumsq, off);
    if ((tid & 31) == 0) red[tid >> 5] = sumsq;
    __syncthreads();
    if (tid < 32) {
        float v = (tid < 8) ? red[tid] : 0.f;
        #pragma unroll
        for (int off = 16; off; off >>= 1)
            v += __shfl_down_sync(0xffffffffu, v, off);
        if (tid == 0) red[32] = v;
    }
    __syncthreads();
    float scale = magnitude[o] * rsqrtf(red[32]);
    cnt = 0;
    for (int d = tid; d < D_IN; d += 256, ++cnt)
        g_Wh[(size_t)o * D_IN + d] = __float2half(wv[cnt] * scale);
}

// x -> fp16 (single term)
__global__ void conv_x_kernel(const float* __restrict__ x, size_t n4) {
    size_t i = (size_t)blockIdx.x * blockDim.x + threadIdx.x;
    size_t stride = (size_t)gridDim.x * blockDim.x;
    const float4* x4 = (const float4*)x;
    __half2* xh2 = (__half2*)g_Xh;
    for (; i < n4; i += stride) {
        float4 v = x4[i];
        xh2[2 * i]     = __halves2half2(__float2half(v.x), __float2half(v.y));
        xh2[2 * i + 1] = __halves2half2(__float2half(v.z), __float2half(v.w));
    }
}

// ============================ HMMA GEMM (single fp16 term) ============
// out = Xh@Wh^T, fp32 accum. CTA tile 128x128, 4 warps (2x2), warp tile
// 64x64; K-chunk 32; 4-stage cp.async (16KB/stage, 64KB/CTA), 2 CTAs/SM.
#define BM 128
#define BN 128
#define BK 32
#define STAGES 4
#define AT_BYTES (BM * 64)            // 8 KB
#define BT_BYTES (BN * 64)            // 8 KB
#define STAGE_BYTES (AT_BYTES + BT_BYTES)       // 16 KB
#define SMEM_TOTAL (STAGES * STAGE_BYTES)       // 64 KB
#define A_OFF 0
#define B_OFF AT_BYTES

__device__ __forceinline__ uint32_t smem_u32(const void* p) {
    uint32_t a;
    asm("{ .reg .u64 t; cvta.to.shared.u64 t, %1; cvt.u32.u64 %0, t; }"
        : "=r"(a) : "l"(p));
    return a;
}
__device__ __forceinline__ void cp16(uint32_t dst, const void* src) {
    asm volatile("cp.async.cg.shared.global [%0], [%1], 16;"
                 :: "r"(dst), "l"(src) : "memory");
}
__device__ __forceinline__ void cp_commit() {
    asm volatile("cp.async.commit_group;" ::: "memory");
}
template <int N_>
__device__ __forceinline__ void cp_wait() {
    asm volatile("cp.async.wait_group %0;" :: "n"(N_) : "memory");
}
__device__ __forceinline__ void ldsm_x4(uint32_t& r0, uint32_t& r1,
                                        uint32_t& r2, uint32_t& r3, uint32_t a) {
    asm volatile("ldmatrix.sync.aligned.m8n8.x4.shared.b16 {%0,%1,%2,%3}, [%4];"
                 : "=r"(r0), "=r"(r1), "=r"(r2), "=r"(r3) : "r"(a));
}
__device__ __forceinline__ void mma16816(float* c, const uint32_t* a,
                                         uint32_t b0, uint32_t b1) {
    asm volatile(
        "mma.sync.aligned.m16n8k16.row.col.f32.f16.f16.f32 "
        "{%0,%1,%2,%3}, {%4,%5,%6,%7}, {%8,%9}, {%0,%1,%2,%3};"
        : "+f"(c[0]), "+f"(c[1]), "+f"(c[2]), "+f"(c[3])
        : "r"(a[0]), "r"(a[1]), "r"(a[2]), "r"(a[3]), "r"(b0), "r"(b1));
}
// swizzled byte offset within a tile: row = 4 x 16B chunks, XOR by (row>>1)&3
__device__ __forceinline__ uint32_t sw_off(int row, int ch) {
    return (uint32_t)(row * 64 + ((ch ^ ((row >> 1) & 3)) * 16));
}

__global__ void __launch_bounds__(128, 2)
gemm_hmma_kernel(float* __restrict__ out, int M, int N, int K) {
    extern __shared__ char smem[];
    const uint32_t sb = smem_u32(smem);
    const int tid = threadIdx.x;
    const int wid = tid >> 5;
    const int lane = tid & 31;
    const int wm = (wid & 1) * 64;
    const int wn = (wid >> 1) * 64;
    const int m0 = blockIdx.y * BM;
    const int n0 = blockIdx.x * BN;

    const int nchunk = K / BK;   // 32

    auto issue = [&](int c, int stage) {
        int kofs = c * BK;
        uint32_t base = sb + stage * STAGE_BYTES;
        #pragma unroll
        for (int j = 0; j < 4; ++j) {
            int u = tid + 128 * j;
            int row = u >> 2, ch = u & 3;
            size_t gofs = (size_t)(m0 + row) * K + kofs + ch * 8;
            cp16(base + A_OFF + sw_off(row, ch), g_Xh + gofs);
        }
        #pragma unroll
        for (int j = 0; j < 4; ++j) {
            int u = tid + 128 * j;
            int row = u >> 2, ch = u & 3;
            size_t gofs = (size_t)(n0 + row) * K + kofs + ch * 8;
            cp16(base + B_OFF + sw_off(row, ch), g_Wh + gofs);
        }
        cp_commit();
    };

    float acc[4][8][4];
    #pragma unroll
    for (int i = 0; i < 4; ++i)
        #pragma unroll
        for (int j = 0; j < 8; ++j)
            #pragma unroll
            for (int q = 0; q < 4; ++q) acc[i][j][q] = 0.f;

    issue(0, 0); issue(1, 1); issue(2, 2);

    for (int c = 0; c < nchunk; ++c) {
        cp_wait<STAGES - 2>();
        __syncthreads();
        if (c + 3 < nchunk) issue(c + 3, (c + 3) % STAGES);

        uint32_t base = sb + (c % STAGES) * STAGE_BYTES;

        #pragma unroll
        for (int h = 0; h < 2; ++h) {
            const int ch = h * 2 + (lane >> 4);
            uint32_t ah[4][4], bh[4][4];
            #pragma unroll
            for (int mf = 0; mf < 4; ++mf) {
                int row = wm + mf * 16 + (lane & 15);
                ldsm_x4(ah[mf][0], ah[mf][1], ah[mf][2], ah[mf][3],
                        base + A_OFF + sw_off(row, ch));
            }
            #pragma unroll
            for (int p = 0; p < 4; ++p) {
                int row = wn + p * 16 + (lane & 15);
                ldsm_x4(bh[p][0], bh[p][1], bh[p][2], bh[p][3],
                        base + B_OFF + sw_off(row, ch));
            }
            #pragma unroll
            for (int mf = 0; mf < 4; ++mf)
                #pragma unroll
                for (int p = 0; p < 4; ++p) {
                    mma16816(acc[mf][2 * p],     ah[mf], bh[p][0], bh[p][2]);
                    mma16816(acc[mf][2 * p + 1], ah[mf], bh[p][1], bh[p][3]);
                }
        }
    }
    cp_wait<0>();

    // Epilogue: direct float2 stores from fragments
    #pragma unroll
    for (int mf = 0; mf < 4; ++mf) {
        int rbase = m0 + wm + mf * 16 + (lane >> 2);
        #pragma unroll
        for (int nf = 0; nf < 8; ++nf) {
            int cbase = n0 + wn + nf * 8 + (lane & 3) * 2;
            float* p0 = out + (size_t)rbase * N + cbase;
            float* p1 = out + (size_t)(rbase + 8) * N + cbase;
            *(float2*)p0 = make_float2(acc[mf][nf][0], acc[mf][nf][1]);
            *(float2*)p1 = make_float2(acc[mf][nf][2], acc[mf][nf][3]);
        }
    }
}

// ============================ launch ============================
extern "C" void kernel_launch(void* const* d_in, const int* in_sizes, int n_in,
                              void* d_out, int out_size) {
    const float* x      = (const float*)d_in[0];
    const float* weight = (const float*)d_in[1];
    const float* a_w    = (const float*)d_in[2];
    const float* b_w    = (const float*)d_in[3];
    const float* mag    = (const float*)d_in[4];
    float* out          = (float*)d_out;

    int D_OUT = in_sizes[4];
    int R     = in_sizes[3] / D_OUT;
    int D_IN  = in_sizes[2] / R;
    int M     = in_sizes[0] / D_IN;

    cudaFuncSetAttribute(gemm_hmma_kernel,
                         cudaFuncAttributeMaxDynamicSharedMemorySize, SMEM_TOTAL);

    prep_kernel<<<D_OUT, 256>>>(weight, a_w, b_w, mag, D_IN, R);
    size_t n4 = ((size_t)M * D_IN) / 4;
    conv_x_kernel<<<2048, 256>>>(x, n4);

    dim3 grid(D_OUT / BN, M / BM);
    gemm_hmma_kernel<<<grid, 128, SMEM_TOTAL>>>(out, M, D_OUT, D_IN);
}

// round 11
// speedup vs baseline: 6.0700x; 1.0443x over previous
#include <cuda_runtime.h>
#include <cuda_fp16.h>
#include <stdint.h>
#include <math.h>

#define SCALING 2.0f
#define MAXM 32768
#define MAXD 1024

// Static scratch (allocation-free per harness rules)
__device__ __half g_Xh[(size_t)MAXM * MAXD];
__device__ __half g_Wh[(size_t)MAXD * MAXD];

// ==================== Fused prep (W-rows) + X conversion ====================
// Blocks [0, D_OUT): build one scaled effective weight row, round to fp16.
// Blocks [D_OUT, D_OUT + CONVB): grid-stride convert x -> fp16.
#define CONVB 2048

__global__ void prep_conv_kernel(const float* __restrict__ weight,
                                 const float* __restrict__ a_w,
                                 const float* __restrict__ b_w,
                                 const float* __restrict__ magnitude,
                                 const float* __restrict__ x,
                                 size_t n4, int D_OUT, int D_IN, int R) {
    int tid = threadIdx.x;
    if (blockIdx.x >= (unsigned)D_OUT) {
        // ---- x conversion part ----
        size_t i = (size_t)(blockIdx.x - D_OUT) * blockDim.x + tid;
        size_t stride = (size_t)CONVB * blockDim.x;
        const float4* x4 = (const float4*)x;
        __half2* xh2 = (__half2*)g_Xh;
        for (; i < n4; i += stride) {
            float4 v = x4[i];
            xh2[2 * i]     = __halves2half2(__float2half(v.x), __float2half(v.y));
            xh2[2 * i + 1] = __halves2half2(__float2half(v.z), __float2half(v.w));
        }
        return;
    }
    // ---- weight prep part ----
    int o = blockIdx.x;
    __shared__ float bs[32];
    __shared__ float red[33];
    if (tid < R) bs[tid] = b_w[o * R + tid];
    __syncthreads();

    float wv[4];
    float sumsq = 0.f;
    int cnt = 0;
    for (int d = tid; d < D_IN; d += 256, ++cnt) {
        float corr = 0.f;
        #pragma unroll 16
        for (int r = 0; r < R; ++r) corr += bs[r] * a_w[(size_t)r * D_IN + d];
        float w = weight[(size_t)o * D_IN + d] + SCALING * corr;
        wv[cnt] = w;
        sumsq += w * w;
    }
    #pragma unroll
    for (int off = 16; off; off >>= 1)
        sumsq += __shfl_down_sync(0xffffffffu, sumsq, off);
    if ((tid & 31) == 0) red[tid >> 5] = sumsq;
    __syncthreads();
    if (tid < 32) {
        float v = (tid < 8) ? red[tid] : 0.f;
        #pragma unroll
        for (int off = 16; off; off >>= 1)
            v += __shfl_down_sync(0xffffffffu, v, off);
        if (tid == 0) red[32] = v;
    }
    __syncthreads();
    float scale = magnitude[o] * rsqrtf(red[32]);
    cnt = 0;
    for (int d = tid; d < D_IN; d += 256, ++cnt)
        g_Wh[(size_t)o * D_IN + d] = __float2half(wv[cnt] * scale);
}

// ============================ HMMA GEMM ============================
// out = Xh@Wh^T, fp32 accum. CTA tile 128x128, 8 warps (2m x 4n), warp tile
// 64x32; K-chunk 32; 4-stage cp.async (16KB/stage, 64KB/CTA), 2 CTAs/SM
// -> 4 warps per SMSP for HMMA latency hiding.
#define BM 128
#define BN 128
#define BK 32
#define STAGES 4
#define AT_BYTES (BM * 64)
#define BT_BYTES (BN * 64)
#define STAGE_BYTES (AT_BYTES + BT_BYTES)       // 16 KB
#define SMEM_TOTAL (STAGES * STAGE_BYTES)       // 64 KB
#define A_OFF 0
#define B_OFF AT_BYTES

__device__ __forceinline__ uint32_t smem_u32(const void* p) {
    uint32_t a;
    asm("{ .reg .u64 t; cvta.to.shared.u64 t, %1; cvt.u32.u64 %0, t; }"
        : "=r"(a) : "l"(p));
    return a;
}
__device__ __forceinline__ void cp16(uint32_t dst, const void* src) {
    asm volatile("cp.async.cg.shared.global [%0], [%1], 16;"
                 :: "r"(dst), "l"(src) : "memory");
}
__device__ __forceinline__ void cp_commit() {
    asm volatile("cp.async.commit_group;" ::: "memory");
}
template <int N_>
__device__ __forceinline__ void cp_wait() {
    asm volatile("cp.async.wait_group %0;" :: "n"(N_) : "memory");
}
__device__ __forceinline__ void ldsm_x4(uint32_t& r0, uint32_t& r1,
                                        uint32_t& r2, uint32_t& r3, uint32_t a) {
    asm volatile("ldmatrix.sync.aligned.m8n8.x4.shared.b16 {%0,%1,%2,%3}, [%4];"
                 : "=r"(r0), "=r"(r1), "=r"(r2), "=r"(r3) : "r"(a));
}
__device__ __forceinline__ void mma16816(float* c, const uint32_t* a,
                                         uint32_t b0, uint32_t b1) {
    asm volatile(
        "mma.sync.aligned.m16n8k16.row.col.f32.f16.f16.f32 "
        "{%0,%1,%2,%3}, {%4,%5,%6,%7}, {%8,%9}, {%0,%1,%2,%3};"
        : "+f"(c[0]), "+f"(c[1]), "+f"(c[2]), "+f"(c[3])
        : "r"(a[0]), "r"(a[1]), "r"(a[2]), "r"(a[3]), "r"(b0), "r"(b1));
}
// swizzled byte offset within a tile: row = 4 x 16B chunks, XOR by (row>>1)&3
__device__ __forceinline__ uint32_t sw_off(int row, int ch) {
    return (uint32_t)(row * 64 + ((ch ^ ((row >> 1) & 3)) * 16));
}

__global__ void __launch_bounds__(256, 2)
gemm_hmma_kernel(float* __restrict__ out, int M, int N, int K) {
    extern __shared__ char smem[];
    const uint32_t sb = smem_u32(smem);
    const int tid = threadIdx.x;
    const int wid = tid >> 5;
    const int lane = tid & 31;
    const int wm = (wid & 1) * 64;        // 2 m-groups
    const int wn = (wid >> 1) * 32;       // 4 n-groups
    const int m0 = blockIdx.y * BM;
    const int n0 = blockIdx.x * BN;

    const int nchunk = K / BK;   // 32

    auto issue = [&](int c, int stage) {
        int kofs = c * BK;
        uint32_t base = sb + stage * STAGE_BYTES;
        #pragma unroll
        for (int j = 0; j < 2; ++j) {
            int u = tid + 256 * j;
            int row = u >> 2, ch = u & 3;
            size_t gofs = (size_t)(m0 + row) * K + kofs + ch * 8;
            cp16(base + A_OFF + sw_off(row, ch), g_Xh + gofs);
        }
        #pragma unroll
        for (int j = 0; j < 2; ++j) {
            int u = tid + 256 * j;
            int row = u >> 2, ch = u & 3;
            size_t gofs = (size_t)(n0 + row) * K + kofs + ch * 8;
            cp16(base + B_OFF + sw_off(row, ch), g_Wh + gofs);
        }
        cp_commit();
    };

    float acc[4][4][4];
    #pragma unroll
    for (int i = 0; i < 4; ++i)
        #pragma unroll
        for (int j = 0; j < 4; ++j)
            #pragma unroll
            for (int q = 0; q < 4; ++q) acc[i][j][q] = 0.f;

    issue(0, 0); issue(1, 1); issue(2, 2);

    for (int c = 0; c < nchunk; ++c) {
        cp_wait<STAGES - 2>();
        __syncthreads();
        if (c + 3 < nchunk) issue(c + 3, (c + 3) % STAGES);

        uint32_t base = sb + (c % STAGES) * STAGE_BYTES;

        #pragma unroll
        for (int h = 0; h < 2; ++h) {
            const int ch = h * 2 + (lane >> 4);
            uint32_t ah[4][4], bh[2][4];
            #pragma unroll
            for (int mf = 0; mf < 4; ++mf) {
                int row = wm + mf * 16 + (lane & 15);
                ldsm_x4(ah[mf][0], ah[mf][1], ah[mf][2], ah[mf][3],
                        base + A_OFF + sw_off(row, ch));
            }
            #pragma unroll
            for (int p = 0; p < 2; ++p) {
                int row = wn + p * 16 + (lane & 15);
                ldsm_x4(bh[p][0], bh[p][1], bh[p][2], bh[p][3],
                        base + B_OFF + sw_off(row, ch));
            }
            #pragma unroll
            for (int mf = 0; mf < 4; ++mf)
                #pragma unroll
                for (int p = 0; p < 2; ++p) {
                    mma16816(acc[mf][2 * p],     ah[mf], bh[p][0], bh[p][2]);
                    mma16816(acc[mf][2 * p + 1], ah[mf], bh[p][1], bh[p][3]);
                }
        }
    }
    cp_wait<0>();

    // Epilogue: direct float2 stores from fragments
    #pragma unroll
    for (int mf = 0; mf < 4; ++mf) {
        int rbase = m0 + wm + mf * 16 + (lane >> 2);
        #pragma unroll
        for (int nf = 0; nf < 4; ++nf) {
            int cbase = n0 + wn + nf * 8 + (lane & 3) * 2;
            float* p0 = out + (size_t)rbase * N + cbase;
            float* p1 = out + (size_t)(rbase + 8) * N + cbase;
            *(float2*)p0 = make_float2(acc[mf][nf][0], acc[mf][nf][1]);
            *(float2*)p1 = make_float2(acc[mf][nf][2], acc[mf][nf][3]);
        }
    }
}

// ============================ launch ============================
extern "C" void kernel_launch(void* const* d_in, const int* in_sizes, int n_in,
                              void* d_out, int out_size) {
    const float* x      = (const float*)d_in[0];
    const float* weight = (const float*)d_in[1];
    const float* a_w    = (const float*)d_in[2];
    const float* b_w    = (const float*)d_in[3];
    const float* mag    = (const float*)d_in[4];
    float* out          = (float*)d_out;

    int D_OUT = in_sizes[4];
    int R     = in_sizes[3] / D_OUT;
    int D_IN  = in_sizes[2] / R;
    int M     = in_sizes[0] / D_IN;

    cudaFuncSetAttribute(gemm_hmma_kernel,
                         cudaFuncAttributeMaxDynamicSharedMemorySize, SMEM_TOTAL);

    size_t n4 = ((size_t)M * D_IN) / 4;
    prep_conv_kernel<<<D_OUT + CONVB, 256>>>(weight, a_w, b_w, mag, x,
                                             n4, D_OUT, D_IN, R);

    dim3 grid(D_OUT / BN, M / BM);
    gemm_hmma_kernel<<<grid, 256, SMEM_TOTAL>>>(out, M, D_OUT, D_IN);
}